// round 1
// baseline (speedup 1.0000x reference)
#include <cuda_runtime.h>
#include <math.h>

#define NKNOT 1024
#define NW    1020   // NUM_KNOTS - DEGREE - 1
#define NINT  1023   // intervals

__global__ __launch_bounds__(256) void bspline_act_kernel(
    const float* __restrict__ x,
    const float* __restrict__ w,
    float* __restrict__ out,
    int n)
{
    // knots extended by 2 virtual uniform knots on each side: s_knot[j] = knot(j-2)
    __shared__ float s_knot[NKNOT + 4];
    __shared__ float s_w[NW];

    const double PI_D = 3.14159265358979323846264338327950288;
    const double STEP = (2.0 * PI_D) / 1023.0;

    for (int j = threadIdx.x; j < NKNOT + 4; j += blockDim.x) {
        int jj = j - 2;
        double v = fma((double)jj, STEP, -PI_D);
        float f = (float)v;
        if (jj == 1023) f = (float)PI_D;   // np.linspace pins the endpoint exactly
        s_knot[j] = f;
    }
    for (int j = threadIdx.x; j < NW; j += blockDim.x) s_w[j] = w[j];
    __syncthreads();

    const float tlo = s_knot[2];           // t[0]
    const float thi = s_knot[2 + 1023];    // t[1023]
    const double INVH = 1023.0 / (2.0 * PI_D);

    int base = (blockIdx.x * blockDim.x + threadIdx.x) * 4;
    if (base >= n) return;

    float4 xv = *reinterpret_cast<const float4*>(x + base);
    float xs[4] = {xv.x, xv.y, xv.z, xv.w};
    float r[4];

#pragma unroll
    for (int e = 0; e < 4; e++) {
        float xx = xs[e];
        float res = 0.0f;
        if (xx >= tlo && xx < thi) {
            // interval index: t[i] <= x < t[i+1]
            int i = (int)floor(((double)xx + PI_D) * INVH);
            i = min(max(i, 0), NINT - 1);
            // fixup against the exact fp32 knot values (half-open, matches reference)
            while (i > 0 && xx < s_knot[i + 2]) --i;
            while (i < NINT - 1 && xx >= s_knot[i + 3]) ++i;

            // knots t[i-2..i+3]  (virtual uniform knots are fine at the edges:
            // every basis function whose weight we actually use depends only on
            // real knots, and the uniform lattice makes virtual == extrapolated)
            const float tm2 = s_knot[i + 0];
            const float tm1 = s_knot[i + 1];
            const float t0  = s_knot[i + 2];
            const float t1  = s_knot[i + 3];
            const float t2  = s_knot[i + 4];
            const float t3  = s_knot[i + 5];

            const float left1  = xx - t0,  left2  = xx - tm1, left3  = xx - tm2;
            const float right1 = t1 - xx,  right2 = t2 - xx,  right3 = t3 - xx;

            // de Boor triangle (NURBS-book basisfuns), N[j] = B_{i-3+j,3}(x)
            float N0 = 1.0f, N1, N2, N3;
            { // k = 1
                float temp = N0 / (right1 + left1);
                N0 = right1 * temp;
                N1 = left1 * temp;
            }
            { // k = 2
                float saved = 0.0f, temp;
                temp = N0 / (right1 + left2); N0 = saved + right1 * temp; saved = left2 * temp;
                temp = N1 / (right2 + left1); N1 = saved + right2 * temp; saved = left1 * temp;
                N2 = saved;
            }
            { // k = 3
                float saved = 0.0f, temp;
                temp = N0 / (right1 + left3); N0 = saved + right1 * temp; saved = left3 * temp;
                temp = N1 / (right2 + left2); N1 = saved + right2 * temp; saved = left2 * temp;
                temp = N2 / (right3 + left1); N2 = saved + right3 * temp; saved = left1 * temp;
                N3 = saved;
            }

            const int c0 = i - 3;  // weight/basis column of N0
            if (c0     >= 0 && c0     < NW) res = fmaf(N0, s_w[c0],     res);
            if (c0 + 1 >= 0 && c0 + 1 < NW) res = fmaf(N1, s_w[c0 + 1], res);
            if (c0 + 2 >= 0 && c0 + 2 < NW) res = fmaf(N2, s_w[c0 + 2], res);
            if (c0 + 3 >= 0 && c0 + 3 < NW) res = fmaf(N3, s_w[c0 + 3], res);
        }
        r[e] = res;
    }

    float4 ov = make_float4(r[0], r[1], r[2], r[3]);
    *reinterpret_cast<float4*>(out + base) = ov;
}

extern "C" void kernel_launch(void* const* d_in, const int* in_sizes, int n_in,
                              void* d_out, int out_size) {
    const float* x = (const float*)d_in[0];
    const float* w = (const float*)d_in[1];
    float* out = (float*)d_out;
    int n = in_sizes[0];            // 262144 (x is [N,1])
    int threads = 256;
    int blocks = (n / 4 + threads - 1) / threads;
    bspline_act_kernel<<<blocks, threads>>>(x, w, out, n);
}

// round 2
// speedup vs baseline: 1.6106x; 1.6106x over previous
#include <cuda_runtime.h>
#include <math.h>

#define NKNOT 1024
#define NW    1020   // NUM_KNOTS - DEGREE - 1

// ---------------------------------------------------------------------------
// Compile-time replica of np.linspace(-pi, pi, 1024).astype(float32):
//   step = (stop - start)/1023  (f64)
//   y_i  = fl32( fl64(i*step) + start )   (separate mul/add, no fma — matches numpy)
//   y[1023] = fl32(stop)
// ---------------------------------------------------------------------------
struct KnotTable { float v[NKNOT]; };

constexpr KnotTable make_knots() {
    KnotTable K{};
    const double start = -3.141592653589793;   // nearest f64 to -pi
    const double stop  =  3.141592653589793;
    const double step  = (stop - start) / 1023.0;
    for (int i = 0; i < NKNOT; i++) {
        double m = (double)i * step;   // rounded f64 multiply
        double y = m + start;          // rounded f64 add
        K.v[i] = (float)y;             // round to f32
    }
    K.v[NKNOT - 1] = (float)stop;      // linspace pins the endpoint
    return K;
}

__device__ constexpr KnotTable g_knots = make_knots();

// domain bounds (fp32 images of +/- pi, same as g_knots.v[0] / v[1023])
#define T_LO (-3.14159274101257324218750f)
#define T_HI ( 3.14159274101257324218750f)
// 1023/(2*pi), correctly rounded fp32
#define INV_H 162.81578063964843750f
// pi/h = 511.5 exactly representable
#define S_OFF 511.5f

__global__ __launch_bounds__(512) void bspline_act_kernel(
    const float* __restrict__ x,
    const float* __restrict__ w,
    float* __restrict__ out,
    int n)
{
    int idx = blockIdx.x * blockDim.x + threadIdx.x;
    if (idx >= n) return;

    float xx = __ldg(x + idx);
    float res = 0.0f;

    if (xx >= T_LO && xx < T_HI) {
        // interval estimate: s = x/h + pi/h  (single fma, S_OFF exact)
        float s = fmaf(xx, INV_H, S_OFF);
        int i = (int)s;                       // s >= -eps, trunc == floor after clamp
        i = min(max(i, 0), 1022);

        // local coordinate against the exact (reference-identical) fp32 knot.
        // x - t_i is exact (nearby floats), so u is good to ~1 ulp.
        float ti = __ldg(&g_knots.v[i]);
        float u  = (xx - ti) * INV_H;

        // uniform cubic B-spline blend (sums to 1 identically)
        const float SIXTH = 0.16666666666666666f;
        float omu = 1.0f - u;
        float u2  = u * u;
        float u3  = u2 * u;
        float N0 = omu * omu * omu * SIXTH;
        float N1 = fmaf(3.0f, u3, fmaf(-6.0f, u2, 4.0f)) * SIXTH;
        float N2 = fmaf(-3.0f, u3, fmaf(3.0f, u2, fmaf(3.0f, u, 1.0f))) * SIXTH;
        float N3 = u3 * SIXTH;

        // weights w[i-3 .. i], clamped-load + select-zero at the edges
        int c = i - 3;
        float Ns[4] = {N0, N1, N2, N3};
        float acc = 0.0f;
#pragma unroll
        for (int k = 0; k < 4; k++) {
            int cc = c + k;
            int ca = min(max(cc, 0), NW - 1);
            float wv = __ldg(w + ca);
            wv = (cc >= 0 && cc < NW) ? wv : 0.0f;
            acc = fmaf(Ns[k], wv, acc);
        }
        res = acc;
    }

    out[idx] = res;
}

extern "C" void kernel_launch(void* const* d_in, const int* in_sizes, int n_in,
                              void* d_out, int out_size) {
    const float* x = (const float*)d_in[0];
    const float* w = (const float*)d_in[1];
    float* out = (float*)d_out;
    int n = in_sizes[0];                 // 262144
    int threads = 512;
    int blocks = (n + threads - 1) / threads;
    bspline_act_kernel<<<blocks, threads>>>(x, w, out, n);
}